// round 1
// baseline (speedup 1.0000x reference)
#include <cuda_runtime.h>
#include <math.h>

// ---------------- problem constants ----------------
#define Bb 4
#define Lseq 1024
#define INDIM 46
#define Dm 256
#define DSm 64
#define Kc 4
#define NLAY 4
#define DI 512          // EXP*D
#define HDm 64
#define Hh 8            // DI/HD
#define XBCd 640        // DI + 2*DS
#define DIPd 1160       // 2*DI + 2*DS + H
#define DFFd 512
#define AHn 4
#define AHDd 64
#define ROWS (Bb*Lseq)  // 4096

// ---------------- device scratch (no allocation allowed) ----------------
__device__ float g_h[ROWS*Dm];
__device__ float g_lnbuf[ROWS*Dm];
__device__ float g_zx[ROWS*DIPd];
__device__ float g_xbc[ROWS*XBCd];
__device__ float g_dt[Bb*Hh*Lseq];
__device__ float g_cA[Bb*Hh*Lseq];
__device__ float g_y[ROWS*DI];
__device__ float g_qkv[ROWS*3*Dm];
__device__ float g_scores[(size_t)Bb*AHn*Lseq*Lseq];   // 64 MB
__device__ float g_attnO[ROWS*Dm];
__device__ float g_ff1[ROWS*2*DFFd];
__device__ float g_ff2[ROWS*DFFd];
__device__ float g_hm[Bb*Dm];

// ---------------- small math helpers ----------------
__device__ __forceinline__ float siluf(float x){ return x / (1.f + expf(-x)); }
__device__ __forceinline__ float geluf(float x){ return 0.5f*x*(1.f + erff(x*0.70710678118654752f)); }

// ---------------- embed: h = x@in_w + in_b + pos ----------------
__global__ void embed_kernel(const float* __restrict__ x,
                             const float* __restrict__ in_w,
                             const float* __restrict__ in_b,
                             const float* __restrict__ pos){
    int row = blockIdx.x;          // b*L + l
    int d = threadIdx.x;           // 0..255
    __shared__ float xr[INDIM];
    if (d < INDIM) xr[d] = x[(size_t)row*INDIM + d];
    __syncthreads();
    float acc = in_b[d];
#pragma unroll
    for (int i = 0; i < INDIM; i++) acc += xr[i]*in_w[i*Dm + d];
    int l = row & (Lseq-1);
    g_h[(size_t)row*Dm + d] = acc + pos[(size_t)l*Dm + d];
}

// ---------------- layernorm over D=256, one block per row ----------------
__global__ void ln_kernel(const float* __restrict__ X,
                          const float* __restrict__ w,
                          const float* __restrict__ b,
                          float* __restrict__ out){
    int row = blockIdx.x; int t = threadIdx.x;
    __shared__ float red[256];
    float v = X[(size_t)row*Dm + t];
    red[t] = v; __syncthreads();
    for (int s = 128; s > 0; s >>= 1){ if (t < s) red[t] += red[t+s]; __syncthreads(); }
    float m = red[0]*(1.f/Dm);
    __syncthreads();
    float d0 = v - m;
    red[t] = d0*d0; __syncthreads();
    for (int s = 128; s > 0; s >>= 1){ if (t < s) red[t] += red[t+s]; __syncthreads(); }
    float var = red[0]*(1.f/Dm);
    out[(size_t)row*Dm + t] = d0*rsqrtf(var + 1e-5f)*w[t] + b[t];
}

// ---------------- generic SGEMM: C(=|+=) A(MxK) @ W(KxN) + bias ----------------
// 64x64 tile, 256 threads, 4x4 microtile. K % 16 == 0, M % 64 == 0, N % 4 == 0.
__global__ void gemm_kernel(const float* __restrict__ A,
                            const float* __restrict__ W,
                            const float* __restrict__ bias,
                            float* __restrict__ C,
                            int K, int N, int addC){
    __shared__ float As[16][64];
    __shared__ float Ws[16][68];
    int tid = threadIdx.x;
    int col0 = blockIdx.x*64, row0 = blockIdx.y*64;
    int ty = tid >> 4, tx = tid & 15;
    int lr = tid >> 2, lk = (tid & 3)*4;     // A loader
    int wk = tid >> 4, wn = (tid & 15)*4;    // W loader
    float acc[4][4] = {};
    for (int k0 = 0; k0 < K; k0 += 16){
        float4 av = *reinterpret_cast<const float4*>(A + (size_t)(row0+lr)*K + k0 + lk);
        As[lk  ][lr] = av.x; As[lk+1][lr] = av.y; As[lk+2][lr] = av.z; As[lk+3][lr] = av.w;
        float4 wv = make_float4(0.f,0.f,0.f,0.f);
        if (col0 + wn + 4 <= N)
            wv = *reinterpret_cast<const float4*>(W + (size_t)(k0+wk)*N + col0 + wn);
        Ws[wk][wn] = wv.x; Ws[wk][wn+1] = wv.y; Ws[wk][wn+2] = wv.z; Ws[wk][wn+3] = wv.w;
        __syncthreads();
#pragma unroll
        for (int k = 0; k < 16; k++){
            float a[4], w[4];
#pragma unroll
            for (int i = 0; i < 4; i++) a[i] = As[k][ty*4+i];
#pragma unroll
            for (int j = 0; j < 4; j++) w[j] = Ws[k][tx*4+j];
#pragma unroll
            for (int i = 0; i < 4; i++)
#pragma unroll
                for (int j = 0; j < 4; j++) acc[i][j] += a[i]*w[j];
        }
        __syncthreads();
    }
#pragma unroll
    for (int i = 0; i < 4; i++){
        int r = row0 + ty*4 + i;
#pragma unroll
        for (int j = 0; j < 4; j++){
            int c = col0 + tx*4 + j;
            if (c < N){
                float v = acc[i][j];
                if (bias) v += bias[c];
                size_t idx = (size_t)r*N + c;
                if (addC) C[idx] += v; else C[idx] = v;
            }
        }
    }
}

// ---------------- causal depthwise conv (K=4) + bias + silu ----------------
__global__ void conv_silu_kernel(const float* __restrict__ cw,
                                 const float* __restrict__ cb){
    int c = blockIdx.x*128 + threadIdx.x;    // 0..639
    int row = blockIdx.y;                    // b*L + l
    int l = row & (Lseq-1);
    float acc = cb[c];
#pragma unroll
    for (int k = 0; k < Kc; k++){
        int ls = l + k - (Kc-1);
        if (ls >= 0)
            acc += g_zx[(size_t)(row + k - (Kc-1))*DIPd + DI + c] * cw[k*XBCd + c];
    }
    g_xbc[(size_t)row*XBCd + c] = siluf(acc);
}

// ---------------- dt softplus + a values ----------------
__global__ void dtprep_kernel(const float* __restrict__ dt_bias,
                              const float* __restrict__ A_log){
    int idx = blockIdx.x*256 + threadIdx.x;  // B*L*H = 32768
    int h  = idx & (Hh-1);
    int bl = idx >> 3;
    float raw = g_zx[(size_t)bl*DIPd + DI + XBCd + h] + dt_bias[h];
    float dtv = (raw > 20.f) ? raw : log1pf(expf(raw));
    int b = bl >> 10, l = bl & (Lseq-1);
    g_dt[(b*Hh+h)*Lseq + l] = dtv;
    g_cA[(b*Hh+h)*Lseq + l] = dtv * (-expf(A_log[h]));  // 'a', scanned next
}

// ---------------- inclusive cumsum over L=1024 per (b,h) ----------------
__global__ void cumsum_kernel(){
    int seq = blockIdx.x;        // b*H + h
    int t = threadIdx.x;         // 0..1023
    __shared__ float buf[1024];
    buf[t] = g_cA[(size_t)seq*Lseq + t];
    __syncthreads();
    for (int off = 1; off < 1024; off <<= 1){
        float add = (t >= off) ? buf[t-off] : 0.f;
        __syncthreads();
        buf[t] += add;
        __syncthreads();
    }
    g_cA[(size_t)seq*Lseq + t] = buf[t];
}

// ---------------- fused Mamba2 quadratic form ----------------
// CTA per (t-tile, head, batch). y[t,p] = sum_{s<=t} exp(cA_t-cA_s)*(C_t·B_s)*dt_s * x[s,p] + D_h*x[t,p]
#define MAMBA_SMEM ((64*65*2 + 64*64 + 3*64)*4)
__global__ void mamba_kernel(const float* __restrict__ Dvec){
    extern __shared__ float sm[];
    float* Ct   = sm;               // [64][65]  C tile (persistent)
    float* BsSt = Ct + 64*65;       // [64][65]  B tile, reused as S tile
    float* Xs   = BsSt + 64*65;     // [64][64]  X tile
    float* cAt  = Xs + 64*64;       // [64]
    float* cAs  = cAt + 64;         // [64]
    float* dss  = cAs + 64;         // [64]
    int tt = blockIdx.x, h = blockIdx.y, b = blockIdx.z;
    int tid = threadIdx.x;
    int ty = tid >> 4, tx = tid & 15;

    for (int e = tid; e < 64*64; e += 256){
        int t = e >> 6, n = e & 63;
        Ct[t*65+n] = g_xbc[(size_t)(b*Lseq + tt*64 + t)*XBCd + DI + DSm + n];
    }
    if (tid < 64) cAt[tid] = g_cA[(b*Hh+h)*Lseq + tt*64 + tid];

    float yacc[4][4] = {};
    for (int st = 0; st <= tt; st++){
        __syncthreads();   // Ct/cAt ready on first iter; prev-iter reads done otherwise
        for (int e = tid; e < 64*64; e += 256){
            int s = e >> 6, n = e & 63;
            size_t rs = (size_t)(b*Lseq + st*64 + s);
            BsSt[s*65+n] = g_xbc[rs*XBCd + DI + n];
            Xs[s*64+n]   = g_xbc[rs*XBCd + h*HDm + n];
        }
        if (tid < 64){
            cAs[tid] = g_cA[(b*Hh+h)*Lseq + st*64 + tid];
            dss[tid] = g_dt[(b*Hh+h)*Lseq + st*64 + tid];
        }
        __syncthreads();
        // CB tile = C_t · B_s^T
        float cb[4][4] = {};
#pragma unroll 8
        for (int n = 0; n < 64; n++){
            float cv[4], bv[4];
#pragma unroll
            for (int i = 0; i < 4; i++) cv[i] = Ct[(ty*4+i)*65 + n];
#pragma unroll
            for (int j = 0; j < 4; j++) bv[j] = BsSt[(tx*4+j)*65 + n];
#pragma unroll
            for (int i = 0; i < 4; i++)
#pragma unroll
                for (int j = 0; j < 4; j++) cb[i][j] += cv[i]*bv[j];
        }
        __syncthreads();   // done reading B, reuse buffer for S
        bool diag = (st == tt);
#pragma unroll
        for (int i = 0; i < 4; i++){
            int tl = ty*4 + i;
#pragma unroll
            for (int j = 0; j < 4; j++){
                int sl = tx*4 + j;
                float v = 0.f;
                if (!diag || sl <= tl)
                    v = expf(cAt[tl] - cAs[sl]) * cb[i][j] * dss[sl];
                BsSt[tl*65 + sl] = v;
            }
        }
        __syncthreads();
        // y += S @ X
#pragma unroll 8
        for (int s = 0; s < 64; s++){
            float sv[4], xv[4];
#pragma unroll
            for (int i = 0; i < 4; i++) sv[i] = BsSt[(ty*4+i)*65 + s];
#pragma unroll
            for (int j = 0; j < 4; j++) xv[j] = Xs[s*64 + tx*4 + j];
#pragma unroll
            for (int i = 0; i < 4; i++)
#pragma unroll
                for (int j = 0; j < 4; j++) yacc[i][j] += sv[i]*xv[j];
        }
    }
    __syncthreads();
    // D-term: reload x at the t rows
    for (int e = tid; e < 64*64; e += 256){
        int t = e >> 6, n = e & 63;
        Xs[t*64+n] = g_xbc[(size_t)(b*Lseq + tt*64 + t)*XBCd + h*HDm + n];
    }
    __syncthreads();
    float Dh = Dvec[h];
#pragma unroll
    for (int i = 0; i < 4; i++){
        int tl = ty*4 + i;
#pragma unroll
        for (int j = 0; j < 4; j++){
            int pl = tx*4 + j;
            float v = yacc[i][j] + Dh * Xs[tl*64 + pl];
            g_y[(size_t)(b*Lseq + tt*64 + tl)*DI + h*HDm + pl] = v;
        }
    }
}

// ---------------- gated RMS norm: y = (y*silu(z)) * rsqrt(mean(sq)+eps) * nw ----------------
__global__ void gated_rms_kernel(const float* __restrict__ nw){
    int row = blockIdx.x; int t = threadIdx.x;
    __shared__ float red[256];
    float z0 = g_zx[(size_t)row*DIPd + t];
    float z1 = g_zx[(size_t)row*DIPd + t + 256];
    float y0 = g_y[(size_t)row*DI + t];
    float y1 = g_y[(size_t)row*DI + t + 256];
    float gg0 = y0 * siluf(z0);
    float gg1 = y1 * siluf(z1);
    red[t] = gg0*gg0 + gg1*gg1; __syncthreads();
    for (int s = 128; s > 0; s >>= 1){ if (t < s) red[t] += red[t+s]; __syncthreads(); }
    float scale = rsqrtf(red[0]*(1.f/DI) + 1e-5f);
    g_y[(size_t)row*DI + t]       = gg0*scale*nw[t];
    g_y[(size_t)row*DI + t + 256] = gg1*scale*nw[t+256];
}

// ---------------- attention scores: S = Q K^T / 8 ----------------
__global__ void attn_scores_kernel(){
    __shared__ float Qs[64][65];
    __shared__ float Ks[64][65];
    int tt = blockIdx.x >> 4, st = blockIdx.x & 15;
    int h = blockIdx.y, b = blockIdx.z;
    int tid = threadIdx.x;
    int ty = tid >> 4, tx = tid & 15;
    for (int e = tid; e < 64*64; e += 256){
        int r = e >> 6, p = e & 63;
        Qs[r][p] = g_qkv[(size_t)(b*Lseq + tt*64 + r)*(3*Dm) + h*AHDd + p];
        Ks[r][p] = g_qkv[(size_t)(b*Lseq + st*64 + r)*(3*Dm) + Dm + h*AHDd + p];
    }
    __syncthreads();
    float acc[4][4] = {};
#pragma unroll 8
    for (int p = 0; p < 64; p++){
        float q[4], kk[4];
#pragma unroll
        for (int i = 0; i < 4; i++) q[i] = Qs[ty*4+i][p];
#pragma unroll
        for (int j = 0; j < 4; j++) kk[j] = Ks[tx*4+j][p];
#pragma unroll
        for (int i = 0; i < 4; i++)
#pragma unroll
            for (int j = 0; j < 4; j++) acc[i][j] += q[i]*kk[j];
    }
#pragma unroll
    for (int i = 0; i < 4; i++)
#pragma unroll
        for (int j = 0; j < 4; j++){
            size_t idx = ((size_t)((b*AHn+h)*Lseq + tt*64 + ty*4 + i))*Lseq + st*64 + tx*4 + j;
            g_scores[idx] = acc[i][j]*0.125f;
        }
}

// ---------------- row softmax over L=1024 ----------------
__global__ void softmax_kernel(){
    int row = blockIdx.x; int t = threadIdx.x;
    __shared__ float red[256];
    size_t base = (size_t)row*Lseq;
    float v[4];
#pragma unroll
    for (int k = 0; k < 4; k++) v[k] = g_scores[base + t + k*256];
    float m = fmaxf(fmaxf(v[0],v[1]), fmaxf(v[2],v[3]));
    red[t] = m; __syncthreads();
    for (int s = 128; s > 0; s >>= 1){ if (t < s) red[t] = fmaxf(red[t], red[t+s]); __syncthreads(); }
    m = red[0];
    __syncthreads();
    float ls = 0.f;
#pragma unroll
    for (int k = 0; k < 4; k++){ v[k] = expf(v[k]-m); ls += v[k]; }
    red[t] = ls; __syncthreads();
    for (int s = 128; s > 0; s >>= 1){ if (t < s) red[t] += red[t+s]; __syncthreads(); }
    float inv = 1.f/red[0];
#pragma unroll
    for (int k = 0; k < 4; k++) g_scores[base + t + k*256] = v[k]*inv;
}

// ---------------- PV: O = P @ V  (output laid out (B,L,D)) ----------------
__global__ void attn_pv_kernel(){
    __shared__ float Ps[64][65];
    __shared__ float Vs[64][64];
    int tt = blockIdx.x, h = blockIdx.y, b = blockIdx.z;
    int tid = threadIdx.x;
    int ty = tid >> 4, tx = tid & 15;
    float acc[4][4] = {};
    for (int st = 0; st < 16; st++){
        __syncthreads();
        for (int e = tid; e < 64*64; e += 256){
            int r = e >> 6, p = e & 63;
            Ps[r][p] = g_scores[((size_t)((b*AHn+h)*Lseq + tt*64 + r))*Lseq + st*64 + p];
            Vs[r][p] = g_qkv[(size_t)(b*Lseq + st*64 + r)*(3*Dm) + 2*Dm + h*AHDd + p];
        }
        __syncthreads();
#pragma unroll 8
        for (int s = 0; s < 64; s++){
            float pv[4], vv[4];
#pragma unroll
            for (int i = 0; i < 4; i++) pv[i] = Ps[ty*4+i][s];
#pragma unroll
            for (int j = 0; j < 4; j++) vv[j] = Vs[s][tx*4+j];
#pragma unroll
            for (int i = 0; i < 4; i++)
#pragma unroll
                for (int j = 0; j < 4; j++) acc[i][j] += pv[i]*vv[j];
        }
    }
#pragma unroll
    for (int i = 0; i < 4; i++)
#pragma unroll
        for (int j = 0; j < 4; j++)
            g_attnO[(size_t)(b*Lseq + tt*64 + ty*4 + i)*Dm + h*AHDd + tx*4 + j] = acc[i][j];
}

// ---------------- gMLP gate: ff2 = gelu(x1)*x2 ----------------
__global__ void gelugate_kernel(){
    int idx = blockIdx.x*256 + threadIdx.x;    // ROWS*DFF = 2M
    int row = idx >> 9, c = idx & 511;
    float x1 = g_ff1[(size_t)row*(2*DFFd) + c];
    float x2 = g_ff1[(size_t)row*(2*DFFd) + DFFd + c];
    g_ff2[(size_t)row*DFFd + c] = geluf(x1)*x2;
}

// ---------------- mean over L ----------------
__global__ void mean_kernel(){
    int b = blockIdx.x, d = threadIdx.x;
    float s = 0.f;
    for (int l = 0; l < Lseq; l++) s += g_lnbuf[(size_t)(b*Lseq + l)*Dm + d];
    g_hm[b*Dm + d] = s*(1.f/Lseq);
}

// ---------------- output heads ----------------
__global__ void head_kernel(const float* __restrict__ dw, const float* __restrict__ db,
                            const float* __restrict__ rw, const float* __restrict__ rb,
                            float* __restrict__ out){
    int t = threadIdx.x; if (t >= 24) return;
    int which = t/12; int b = (t%12)/3; int j = t%3;
    const float* W  = which ? rw : dw;
    const float* bs = which ? rb : db;
    float acc = bs[j];
    for (int d = 0; d < Dm; d++) acc += g_hm[b*Dm + d]*W[d*3 + j];
    out[which*12 + b*3 + j] = acc;
}

// ---------------- launch ----------------
extern "C" void kernel_launch(void* const* d_in, const int* in_sizes, int n_in,
                              void* d_out, int out_size){
    const float* x          = (const float*)d_in[0];
    const float* pos_emb    = (const float*)d_in[1];
    const float* in_w       = (const float*)d_in[2];
    const float* in_b       = (const float*)d_in[3];
    const float* ln1_w      = (const float*)d_in[4];
    const float* ln1_b      = (const float*)d_in[5];
    const float* ssm_in_w   = (const float*)d_in[6];
    const float* ssm_conv_w = (const float*)d_in[7];
    const float* ssm_conv_b = (const float*)d_in[8];
    const float* ssm_dt_bias= (const float*)d_in[9];
    const float* ssm_A_log  = (const float*)d_in[10];
    const float* ssm_D      = (const float*)d_in[11];
    const float* ssm_norm_w = (const float*)d_in[12];
    const float* ssm_out_w  = (const float*)d_in[13];
    const float* ln2_w      = (const float*)d_in[14];
    const float* ln2_b      = (const float*)d_in[15];
    const float* fc1_w      = (const float*)d_in[16];
    const float* fc1_b      = (const float*)d_in[17];
    const float* fc2_w      = (const float*)d_in[18];
    const float* fc2_b      = (const float*)d_in[19];
    const float* attn_ln_w  = (const float*)d_in[20];
    const float* attn_ln_b  = (const float*)d_in[21];
    const float* attn_qkv_w = (const float*)d_in[22];
    const float* attn_qkv_b = (const float*)d_in[23];
    const float* attn_out_w = (const float*)d_in[24];
    const float* attn_out_b = (const float*)d_in[25];
    const float* norm_w     = (const float*)d_in[26];
    const float* norm_b     = (const float*)d_in[27];
    const float* dir_w      = (const float*)d_in[28];
    const float* dir_b      = (const float*)d_in[29];
    const float* reg_w      = (const float*)d_in[30];
    const float* reg_b      = (const float*)d_in[31];
    float* out = (float*)d_out;

    cudaFuncSetAttribute(mamba_kernel, cudaFuncAttributeMaxDynamicSharedMemorySize, MAMBA_SMEM);

    float *ph, *pln, *pzx, *py, *pqkv, *pattnO, *pff1, *pff2;
    cudaGetSymbolAddress((void**)&ph,     g_h);
    cudaGetSymbolAddress((void**)&pln,    g_lnbuf);
    cudaGetSymbolAddress((void**)&pzx,    g_zx);
    cudaGetSymbolAddress((void**)&py,     g_y);
    cudaGetSymbolAddress((void**)&pqkv,   g_qkv);
    cudaGetSymbolAddress((void**)&pattnO, g_attnO);
    cudaGetSymbolAddress((void**)&pff1,   g_ff1);
    cudaGetSymbolAddress((void**)&pff2,   g_ff2);

    embed_kernel<<<ROWS, 256>>>(x, in_w, in_b, pos_emb);

    for (int i = 0; i < NLAY; i++){
        // ---- Mamba2 branch ----
        ln_kernel<<<ROWS, 256>>>(ph, ln1_w + i*Dm, ln1_b + i*Dm, pln);
        gemm_kernel<<<dim3((DIPd+63)/64, ROWS/64), 256>>>(
            pln, ssm_in_w + (size_t)i*Dm*DIPd, nullptr, pzx, Dm, DIPd, 0);
        conv_silu_kernel<<<dim3(XBCd/128, ROWS), 128>>>(
            ssm_conv_w + (size_t)i*Kc*XBCd, ssm_conv_b + (size_t)i*XBCd);
        dtprep_kernel<<<(Bb*Lseq*Hh)/256, 256>>>(ssm_dt_bias + i*Hh, ssm_A_log + i*Hh);
        cumsum_kernel<<<Bb*Hh, 1024>>>();
        mamba_kernel<<<dim3(Lseq/64, Hh, Bb), 256, MAMBA_SMEM>>>(ssm_D + i*Hh);
        gated_rms_kernel<<<ROWS, 256>>>(ssm_norm_w + (size_t)i*DI);
        gemm_kernel<<<dim3(Dm/64, ROWS/64), 256>>>(
            py, ssm_out_w + (size_t)i*DI*Dm, nullptr, ph, DI, Dm, 1);

        // ---- attention (odd layers) ----
        if (i & 1){
            int j = i >> 1;
            ln_kernel<<<ROWS, 256>>>(ph, attn_ln_w + j*Dm, attn_ln_b + j*Dm, pln);
            gemm_kernel<<<dim3(3*Dm/64, ROWS/64), 256>>>(
                pln, attn_qkv_w + (size_t)j*Dm*3*Dm, attn_qkv_b + (size_t)j*3*Dm, pqkv, Dm, 3*Dm, 0);
            attn_scores_kernel<<<dim3(256, AHn, Bb), 256>>>();
            softmax_kernel<<<Bb*AHn*Lseq, 256>>>();
            attn_pv_kernel<<<dim3(16, AHn, Bb), 256>>>();
            gemm_kernel<<<dim3(Dm/64, ROWS/64), 256>>>(
                pattnO, attn_out_w + (size_t)j*Dm*Dm, attn_out_b + (size_t)j*Dm, ph, Dm, Dm, 1);
        }

        // ---- gMLP ----
        ln_kernel<<<ROWS, 256>>>(ph, ln2_w + i*Dm, ln2_b + i*Dm, pln);
        gemm_kernel<<<dim3(2*DFFd/64, ROWS/64), 256>>>(
            pln, fc1_w + (size_t)i*Dm*2*DFFd, fc1_b + (size_t)i*2*DFFd, pff1, Dm, 2*DFFd, 0);
        gelugate_kernel<<<(ROWS*DFFd)/256, 256>>>();
        gemm_kernel<<<dim3(Dm/64, ROWS/64), 256>>>(
            pff2, fc2_w + (size_t)i*DFFd*Dm, fc2_b + (size_t)i*Dm, ph, DFFd, Dm, 1);
    }

    // ---- final norm, mean, heads ----
    ln_kernel<<<ROWS, 256>>>(ph, norm_w, norm_b, pln);
    mean_kernel<<<Bb, 256>>>();
    head_kernel<<<1, 32>>>(dir_w, dir_b, reg_w, reg_b, out);
}

// round 2
// speedup vs baseline: 1.0745x; 1.0745x over previous
#include <cuda_runtime.h>
#include <math.h>

// ---------------- problem constants ----------------
#define Bb 4
#define Lseq 1024
#define INDIM 46
#define Dm 256
#define DSm 64
#define Kc 4
#define NLAY 4
#define DI 512          // EXP*D
#define HDm 64
#define Hh 8            // DI/HD
#define XBCd 640        // DI + 2*DS
#define DIPd 1160       // 2*DI + 2*DS + H
#define DFFd 512
#define AHn 4
#define AHDd 64
#define ROWS (Bb*Lseq)  // 4096

// ---------------- device scratch ----------------
__device__ float g_h[ROWS*Dm];
__device__ float g_lnbuf[ROWS*Dm];
__device__ float g_zx[ROWS*DIPd];
__device__ float g_xbc[ROWS*XBCd];
__device__ float g_dt[Bb*Hh*Lseq];
__device__ float g_cA[Bb*Hh*Lseq];
__device__ float g_y[ROWS*DI];
__device__ float g_qkv[ROWS*3*Dm];
__device__ float g_scores[(size_t)Bb*AHn*Lseq*Lseq];   // 64 MB
__device__ float g_attnO[ROWS*Dm];
__device__ float g_ff1[ROWS*2*DFFd];
__device__ float g_ff2[ROWS*DFFd];
__device__ float g_hm[Bb*Dm];

__device__ __forceinline__ float siluf(float x){ return x / (1.f + expf(-x)); }
__device__ __forceinline__ float geluf(float x){ return 0.5f*x*(1.f + erff(x*0.70710678118654752f)); }

// ---------------- embed ----------------
__global__ void embed_kernel(const float* __restrict__ x,
                             const float* __restrict__ in_w,
                             const float* __restrict__ in_b,
                             const float* __restrict__ pos){
    int row = blockIdx.x;
    int d = threadIdx.x;
    __shared__ float xr[INDIM];
    if (d < INDIM) xr[d] = x[(size_t)row*INDIM + d];
    __syncthreads();
    float acc = in_b[d];
#pragma unroll
    for (int i = 0; i < INDIM; i++) acc += xr[i]*in_w[i*Dm + d];
    int l = row & (Lseq-1);
    g_h[(size_t)row*Dm + d] = acc + pos[(size_t)l*Dm + d];
}

// ---------------- layernorm ----------------
__global__ void ln_kernel(const float* __restrict__ X,
                          const float* __restrict__ w,
                          const float* __restrict__ b,
                          float* __restrict__ out){
    int row = blockIdx.x; int t = threadIdx.x;
    __shared__ float red[256];
    float v = X[(size_t)row*Dm + t];
    red[t] = v; __syncthreads();
    for (int s = 128; s > 0; s >>= 1){ if (t < s) red[t] += red[t+s]; __syncthreads(); }
    float m = red[0]*(1.f/Dm);
    __syncthreads();
    float d0 = v - m;
    red[t] = d0*d0; __syncthreads();
    for (int s = 128; s > 0; s >>= 1){ if (t < s) red[t] += red[t+s]; __syncthreads(); }
    float var = red[0]*(1.f/Dm);
    out[(size_t)row*Dm + t] = d0*rsqrtf(var + 1e-5f)*w[t] + b[t];
}

// ---------------- SGEMM 128x128 tile, 8x8 micro, double-buffered ----------------
__global__ __launch_bounds__(256,2)
void gemm128(const float* __restrict__ A, const float* __restrict__ W,
             const float* __restrict__ bias, float* __restrict__ C,
             int K, int N, int addC){
    __shared__ float As[2][16][128];
    __shared__ float Bs[2][16][128];
    int tid = threadIdx.x;
    int row0 = blockIdx.y*128, col0 = blockIdx.x*128;
    int ar = tid>>1, ak = (tid&1)*8;
    int bk = tid>>4, bc = (tid&15)*8;
    int ty = tid>>4, tx = tid&15;
    const float* Ap = A + (size_t)(row0+ar)*K + ak;
    float4 a0,a1,b0,b1;
    a0 = *(const float4*)(Ap);
    a1 = *(const float4*)(Ap+4);
    b0 = make_float4(0.f,0.f,0.f,0.f); b1 = b0;
    if (col0+bc+4 <= N) b0 = *(const float4*)(W + (size_t)bk*N + col0+bc);
    if (col0+bc+8 <= N) b1 = *(const float4*)(W + (size_t)bk*N + col0+bc+4);
    int nt = K>>4;
    As[0][ak+0][ar]=a0.x; As[0][ak+1][ar]=a0.y; As[0][ak+2][ar]=a0.z; As[0][ak+3][ar]=a0.w;
    As[0][ak+4][ar]=a1.x; As[0][ak+5][ar]=a1.y; As[0][ak+6][ar]=a1.z; As[0][ak+7][ar]=a1.w;
    *(float4*)&Bs[0][bk][bc]   = b0;
    *(float4*)&Bs[0][bk][bc+4] = b1;
    __syncthreads();
    float acc[8][8];
#pragma unroll
    for (int i=0;i<8;i++)
#pragma unroll
        for (int j=0;j<8;j++) acc[i][j]=0.f;
    for (int t=0; t<nt; t++){
        if (t+1 < nt){
            int k0 = (t+1)*16;
            a0 = *(const float4*)(Ap + k0);
            a1 = *(const float4*)(Ap + k0 + 4);
            b0 = make_float4(0.f,0.f,0.f,0.f); b1 = b0;
            if (col0+bc+4 <= N) b0 = *(const float4*)(W + (size_t)(k0+bk)*N + col0+bc);
            if (col0+bc+8 <= N) b1 = *(const float4*)(W + (size_t)(k0+bk)*N + col0+bc+4);
        }
        int buf = t&1;
#pragma unroll
        for (int k=0;k<16;k++){
            float4 av0 = *(const float4*)&As[buf][k][ty*8];
            float4 av1 = *(const float4*)&As[buf][k][ty*8+4];
            float4 bv0 = *(const float4*)&Bs[buf][k][tx*4];
            float4 bv1 = *(const float4*)&Bs[buf][k][64+tx*4];
            float a[8] = {av0.x,av0.y,av0.z,av0.w,av1.x,av1.y,av1.z,av1.w};
            float bb[8] = {bv0.x,bv0.y,bv0.z,bv0.w,bv1.x,bv1.y,bv1.z,bv1.w};
#pragma unroll
            for (int i=0;i<8;i++)
#pragma unroll
                for (int j=0;j<8;j++) acc[i][j] += a[i]*bb[j];
        }
        __syncthreads();
        if (t+1 < nt){
            int nb = (t+1)&1;
            As[nb][ak+0][ar]=a0.x; As[nb][ak+1][ar]=a0.y; As[nb][ak+2][ar]=a0.z; As[nb][ak+3][ar]=a0.w;
            As[nb][ak+4][ar]=a1.x; As[nb][ak+5][ar]=a1.y; As[nb][ak+6][ar]=a1.z; As[nb][ak+7][ar]=a1.w;
            *(float4*)&Bs[nb][bk][bc]   = b0;
            *(float4*)&Bs[nb][bk][bc+4] = b1;
            __syncthreads();
        }
    }
#pragma unroll
    for (int half=0; half<2; half++){
        int cbase = col0 + half*64 + tx*4;
        if (cbase + 4 <= N){
            float bx=0.f,by=0.f,bz=0.f,bw=0.f;
            if (bias){ bx=bias[cbase]; by=bias[cbase+1]; bz=bias[cbase+2]; bw=bias[cbase+3]; }
#pragma unroll
            for (int i=0;i<8;i++){
                int r = row0 + ty*8 + i;
                size_t idx = (size_t)r*N + cbase;
                float4 v;
                v.x = acc[i][half*4+0]+bx;
                v.y = acc[i][half*4+1]+by;
                v.z = acc[i][half*4+2]+bz;
                v.w = acc[i][half*4+3]+bw;
                if (addC){
                    float4 o = *(const float4*)&C[idx];
                    v.x+=o.x; v.y+=o.y; v.z+=o.z; v.w+=o.w;
                }
                *(float4*)&C[idx] = v;
            }
        }
    }
}

// ---------------- SGEMM 128x64 tile, 8x4 micro, double-buffered (N mult of 64) ----------------
__global__ __launch_bounds__(256,2)
void gemm64(const float* __restrict__ A, const float* __restrict__ W,
            const float* __restrict__ bias, float* __restrict__ C,
            int K, int N, int addC){
    __shared__ float As[2][16][128];
    __shared__ float Bs[2][16][64];
    int tid = threadIdx.x;
    int row0 = blockIdx.y*128, col0 = blockIdx.x*64;
    int ar = tid>>1, ak = (tid&1)*8;
    int bk = tid>>4, bc = (tid&15)*4;
    int ty = tid>>4, tx = tid&15;
    const float* Ap = A + (size_t)(row0+ar)*K + ak;
    float4 a0,a1,b0;
    a0 = *(const float4*)(Ap);
    a1 = *(const float4*)(Ap+4);
    b0 = *(const float4*)(W + (size_t)bk*N + col0+bc);
    int nt = K>>4;
    As[0][ak+0][ar]=a0.x; As[0][ak+1][ar]=a0.y; As[0][ak+2][ar]=a0.z; As[0][ak+3][ar]=a0.w;
    As[0][ak+4][ar]=a1.x; As[0][ak+5][ar]=a1.y; As[0][ak+6][ar]=a1.z; As[0][ak+7][ar]=a1.w;
    *(float4*)&Bs[0][bk][bc] = b0;
    __syncthreads();
    float acc[8][4];
#pragma unroll
    for (int i=0;i<8;i++)
#pragma unroll
        for (int j=0;j<4;j++) acc[i][j]=0.f;
    for (int t=0; t<nt; t++){
        if (t+1 < nt){
            int k0 = (t+1)*16;
            a0 = *(const float4*)(Ap + k0);
            a1 = *(const float4*)(Ap + k0 + 4);
            b0 = *(const float4*)(W + (size_t)(k0+bk)*N + col0+bc);
        }
        int buf = t&1;
#pragma unroll
        for (int k=0;k<16;k++){
            float4 av0 = *(const float4*)&As[buf][k][ty*8];
            float4 av1 = *(const float4*)&As[buf][k][ty*8+4];
            float4 bv  = *(const float4*)&Bs[buf][k][tx*4];
            float a[8] = {av0.x,av0.y,av0.z,av0.w,av1.x,av1.y,av1.z,av1.w};
#pragma unroll
            for (int i=0;i<8;i++){
                acc[i][0] += a[i]*bv.x;
                acc[i][1] += a[i]*bv.y;
                acc[i][2] += a[i]*bv.z;
                acc[i][3] += a[i]*bv.w;
            }
        }
        __syncthreads();
        if (t+1 < nt){
            int nb = (t+1)&1;
            As[nb][ak+0][ar]=a0.x; As[nb][ak+1][ar]=a0.y; As[nb][ak+2][ar]=a0.z; As[nb][ak+3][ar]=a0.w;
            As[nb][ak+4][ar]=a1.x; As[nb][ak+5][ar]=a1.y; As[nb][ak+6][ar]=a1.z; As[nb][ak+7][ar]=a1.w;
            *(float4*)&Bs[nb][bk][bc] = b0;
            __syncthreads();
        }
    }
    int cbase = col0 + tx*4;
    float bx=0.f,by=0.f,bz=0.f,bw=0.f;
    if (bias){ bx=bias[cbase]; by=bias[cbase+1]; bz=bias[cbase+2]; bw=bias[cbase+3]; }
#pragma unroll
    for (int i=0;i<8;i++){
        int r = row0 + ty*8 + i;
        size_t idx = (size_t)r*N + cbase;
        float4 v;
        v.x = acc[i][0]+bx; v.y = acc[i][1]+by; v.z = acc[i][2]+bz; v.w = acc[i][3]+bw;
        if (addC){
            float4 o = *(const float4*)&C[idx];
            v.x+=o.x; v.y+=o.y; v.z+=o.z; v.w+=o.w;
        }
        *(float4*)&C[idx] = v;
    }
}

// ---------------- conv + silu ----------------
__global__ void conv_silu_kernel(const float* __restrict__ cw,
                                 const float* __restrict__ cb){
    int c = blockIdx.x*128 + threadIdx.x;
    int row = blockIdx.y;
    int l = row & (Lseq-1);
    float acc = cb[c];
#pragma unroll
    for (int k = 0; k < Kc; k++){
        int ls = l + k - (Kc-1);
        if (ls >= 0)
            acc += g_zx[(size_t)(row + k - (Kc-1))*DIPd + DI + c] * cw[k*XBCd + c];
    }
    g_xbc[(size_t)row*XBCd + c] = siluf(acc);
}

// ---------------- fused dt softplus + cumsum ----------------
__global__ __launch_bounds__(1024)
void dtcum_kernel(const float* __restrict__ dt_bias,
                  const float* __restrict__ A_log){
    int bh = blockIdx.x; int b = bh>>3, h = bh&7;
    int l = threadIdx.x;
    __shared__ float buf[1024];
    float raw = g_zx[(size_t)(b*Lseq+l)*DIPd + DI + XBCd + h] + dt_bias[h];
    float dtv = (raw > 20.f) ? raw : log1pf(expf(raw));
    g_dt[(size_t)bh*Lseq + l] = dtv;
    buf[l] = dtv * (-expf(A_log[h]));
    __syncthreads();
    for (int off = 1; off < 1024; off <<= 1){
        float add = (l >= off) ? buf[l-off] : 0.f;
        __syncthreads();
        buf[l] += add;
        __syncthreads();
    }
    g_cA[(size_t)bh*Lseq + l] = buf[l];
}

// ---------------- fused Mamba2 quadratic form (128 thr, 8x4 micro) ----------------
#define MSMEM ((3*64*68 + 3*64)*4)
__global__ __launch_bounds__(128)
void mamba_kernel(const float* __restrict__ Dvec){
    extern __shared__ float sm[];
    float* CtT = sm;             // [n][68] : C transposed
    float* BsS = CtT + 64*68;    // BsT [n][68], then ST [s][68]
    float* Xs  = BsS + 64*68;    // [s][68]
    float* cAt = Xs + 64*68;
    float* cAs = cAt + 64;
    float* dss = cAs + 64;
    int tt = blockIdx.x, h = blockIdx.y, b = blockIdx.z;
    int tid = threadIdx.x;
    int ty = tid>>4, tx = tid&15;
    size_t rowt = (size_t)(b*Lseq + tt*64);

#pragma unroll
    for (int c=0;c<8;c++){
        int idx = c*128 + tid;
        int r = idx>>4, n4 = (idx&15)*4;
        float4 v = *(const float4*)&g_xbc[(rowt + r)*XBCd + DI + DSm + n4];
        CtT[(n4+0)*68 + r] = v.x;
        CtT[(n4+1)*68 + r] = v.y;
        CtT[(n4+2)*68 + r] = v.z;
        CtT[(n4+3)*68 + r] = v.w;
    }
    if (tid < 64) cAt[tid] = g_cA[(size_t)(b*Hh+h)*Lseq + tt*64 + tid];

    float yacc[8][4];
#pragma unroll
    for (int i=0;i<8;i++)
#pragma unroll
        for (int j=0;j<4;j++) yacc[i][j]=0.f;

    for (int st=0; st<=tt; st++){
        __syncthreads();
        size_t rows = (size_t)(b*Lseq + st*64);
#pragma unroll
        for (int c=0;c<8;c++){
            int idx = c*128 + tid;
            int r = idx>>4, n4 = (idx&15)*4;
            float4 bv = *(const float4*)&g_xbc[(rows+r)*XBCd + DI + n4];
            BsS[(n4+0)*68 + r] = bv.x;
            BsS[(n4+1)*68 + r] = bv.y;
            BsS[(n4+2)*68 + r] = bv.z;
            BsS[(n4+3)*68 + r] = bv.w;
            float4 xv = *(const float4*)&g_xbc[(rows+r)*XBCd + h*HDm + n4];
            *(float4*)&Xs[r*68 + n4] = xv;
        }
        if (tid < 64){
            cAs[tid] = g_cA[(size_t)(b*Hh+h)*Lseq + st*64 + tid];
            dss[tid] = g_dt[(size_t)(b*Hh+h)*Lseq + st*64 + tid];
        }
        __syncthreads();
        // CB = C_t . B_s^T  (reduce over n)
        float cb[8][4];
#pragma unroll
        for (int i=0;i<8;i++)
#pragma unroll
            for (int j=0;j<4;j++) cb[i][j]=0.f;
#pragma unroll 8
        for (int n=0;n<64;n++){
            float4 a0 = *(const float4*)&CtT[n*68 + ty*8];
            float4 a1 = *(const float4*)&CtT[n*68 + ty*8 + 4];
            float4 bv = *(const float4*)&BsS[n*68 + tx*4];
            float a[8] = {a0.x,a0.y,a0.z,a0.w,a1.x,a1.y,a1.z,a1.w};
#pragma unroll
            for (int i=0;i<8;i++){
                cb[i][0] += a[i]*bv.x;
                cb[i][1] += a[i]*bv.y;
                cb[i][2] += a[i]*bv.z;
                cb[i][3] += a[i]*bv.w;
            }
        }
        __syncthreads();
        // decay/dt, store S transposed: ST[s][t]
        bool diag = (st == tt);
        float d[8][4];
#pragma unroll
        for (int i=0;i<8;i++){
            int t = ty*8+i;
            float ca = cAt[t];
#pragma unroll
            for (int j=0;j<4;j++){
                int s = tx*4+j;
                float v = 0.f;
                if (!diag || s <= t) v = expf(ca - cAs[s]) * cb[i][j] * dss[s];
                d[i][j] = v;
            }
        }
#pragma unroll
        for (int j=0;j<4;j++){
            int s = tx*4+j;
            float4 v0 = make_float4(d[0][j],d[1][j],d[2][j],d[3][j]);
            float4 v1 = make_float4(d[4][j],d[5][j],d[6][j],d[7][j]);
            *(float4*)&BsS[s*68 + ty*8]   = v0;
            *(float4*)&BsS[s*68 + ty*8+4] = v1;
        }
        __syncthreads();
        // y += S @ X  (reduce over s)
#pragma unroll 8
        for (int s=0;s<64;s++){
            float4 a0 = *(const float4*)&BsS[s*68 + ty*8];
            float4 a1 = *(const float4*)&BsS[s*68 + ty*8 + 4];
            float4 xv = *(const float4*)&Xs[s*68 + tx*4];
            float a[8] = {a0.x,a0.y,a0.z,a0.w,a1.x,a1.y,a1.z,a1.w};
#pragma unroll
            for (int i=0;i<8;i++){
                yacc[i][0] += a[i]*xv.x;
                yacc[i][1] += a[i]*xv.y;
                yacc[i][2] += a[i]*xv.z;
                yacc[i][3] += a[i]*xv.w;
            }
        }
    }
    float Dh = Dvec[h];
#pragma unroll
    for (int i=0;i<8;i++){
        int t = ty*8+i;
        float4 xv = *(const float4*)&g_xbc[(rowt+t)*XBCd + h*HDm + tx*4];
        float4 o;
        o.x = yacc[i][0] + Dh*xv.x;
        o.y = yacc[i][1] + Dh*xv.y;
        o.z = yacc[i][2] + Dh*xv.z;
        o.w = yacc[i][3] + Dh*xv.w;
        *(float4*)&g_y[(rowt+t)*DI + h*HDm + tx*4] = o;
    }
}

// ---------------- gated RMS norm ----------------
__global__ void gated_rms_kernel(const float* __restrict__ nw){
    int row = blockIdx.x; int t = threadIdx.x;
    __shared__ float red[256];
    float z0 = g_zx[(size_t)row*DIPd + t];
    float z1 = g_zx[(size_t)row*DIPd + t + 256];
    float y0 = g_y[(size_t)row*DI + t];
    float y1 = g_y[(size_t)row*DI + t + 256];
    float gg0 = y0 * siluf(z0);
    float gg1 = y1 * siluf(z1);
    red[t] = gg0*gg0 + gg1*gg1; __syncthreads();
    for (int s = 128; s > 0; s >>= 1){ if (t < s) red[t] += red[t+s]; __syncthreads(); }
    float scale = rsqrtf(red[0]*(1.f/DI) + 1e-5f);
    g_y[(size_t)row*DI + t]       = gg0*scale*nw[t];
    g_y[(size_t)row*DI + t + 256] = gg1*scale*nw[t+256];
}

// ---------------- attention scores (128 thr, 8x4 micro) ----------------
__global__ __launch_bounds__(128)
void attn_scores_kernel(){
    __shared__ float QT[64*68];
    __shared__ float KT[64*68];
    int tt = blockIdx.x >> 4, st = blockIdx.x & 15;
    int h = blockIdx.y, b = blockIdx.z;
    int tid = threadIdx.x;
    int ty = tid>>4, tx = tid&15;
#pragma unroll
    for (int c=0;c<8;c++){
        int idx = c*128 + tid;
        int r = idx>>4, p4 = (idx&15)*4;
        float4 q = *(const float4*)&g_qkv[(size_t)(b*Lseq + tt*64 + r)*(3*Dm) + h*AHDd + p4];
        QT[(p4+0)*68 + r] = q.x;
        QT[(p4+1)*68 + r] = q.y;
        QT[(p4+2)*68 + r] = q.z;
        QT[(p4+3)*68 + r] = q.w;
        float4 k = *(const float4*)&g_qkv[(size_t)(b*Lseq + st*64 + r)*(3*Dm) + Dm + h*AHDd + p4];
        KT[(p4+0)*68 + r] = k.x;
        KT[(p4+1)*68 + r] = k.y;
        KT[(p4+2)*68 + r] = k.z;
        KT[(p4+3)*68 + r] = k.w;
    }
    __syncthreads();
    float acc[8][4];
#pragma unroll
    for (int i=0;i<8;i++)
#pragma unroll
        for (int j=0;j<4;j++) acc[i][j]=0.f;
#pragma unroll 8
    for (int p=0;p<64;p++){
        float4 a0 = *(const float4*)&QT[p*68 + ty*8];
        float4 a1 = *(const float4*)&QT[p*68 + ty*8 + 4];
        float4 bv = *(const float4*)&KT[p*68 + tx*4];
        float a[8] = {a0.x,a0.y,a0.z,a0.w,a1.x,a1.y,a1.z,a1.w};
#pragma unroll
        for (int i=0;i<8;i++){
            acc[i][0] += a[i]*bv.x;
            acc[i][1] += a[i]*bv.y;
            acc[i][2] += a[i]*bv.z;
            acc[i][3] += a[i]*bv.w;
        }
    }
    size_t base = ((size_t)((b*AHn+h)*Lseq + tt*64))*Lseq + st*64;
#pragma unroll
    for (int i=0;i<8;i++){
        float4 v = make_float4(acc[i][0]*0.125f, acc[i][1]*0.125f,
                               acc[i][2]*0.125f, acc[i][3]*0.125f);
        *(float4*)&g_scores[base + (size_t)(ty*8+i)*Lseq + tx*4] = v;
    }
}

// ---------------- softmax ----------------
__global__ void softmax_kernel(){
    int row = blockIdx.x; int t = threadIdx.x;
    __shared__ float red[256];
    size_t base = (size_t)row*Lseq;
    float v[4];
#pragma unroll
    for (int k = 0; k < 4; k++) v[k] = g_scores[base + t + k*256];
    float m = fmaxf(fmaxf(v[0],v[1]), fmaxf(v[2],v[3]));
    red[t] = m; __syncthreads();
    for (int s = 128; s > 0; s >>= 1){ if (t < s) red[t] = fmaxf(red[t], red[t+s]); __syncthreads(); }
    m = red[0];
    __syncthreads();
    float ls = 0.f;
#pragma unroll
    for (int k = 0; k < 4; k++){ v[k] = expf(v[k]-m); ls += v[k]; }
    red[t] = ls; __syncthreads();
    for (int s = 128; s > 0; s >>= 1){ if (t < s) red[t] += red[t+s]; __syncthreads(); }
    float inv = 1.f/red[0];
#pragma unroll
    for (int k = 0; k < 4; k++) g_scores[base + t + k*256] = v[k]*inv;
}

// ---------------- PV (128 thr, 8x4 micro) ----------------
__global__ __launch_bounds__(128)
void attn_pv_kernel(){
    __shared__ float PT[64*68];
    __shared__ float Vs[64*68];
    int tt = blockIdx.x, h = blockIdx.y, b = blockIdx.z;
    int tid = threadIdx.x;
    int ty = tid>>4, tx = tid&15;
    float acc[8][4];
#pragma unroll
    for (int i=0;i<8;i++)
#pragma unroll
        for (int j=0;j<4;j++) acc[i][j]=0.f;
    for (int st=0; st<16; st++){
        __syncthreads();
#pragma unroll
        for (int c=0;c<8;c++){
            int idx = c*128 + tid;
            int r = idx>>4, s4 = (idx&15)*4;
            float4 pv = *(const float4*)&g_scores[((size_t)((b*AHn+h)*Lseq + tt*64 + r))*Lseq + st*64 + s4];
            PT[(s4+0)*68 + r] = pv.x;
            PT[(s4+1)*68 + r] = pv.y;
            PT[(s4+2)*68 + r] = pv.z;
            PT[(s4+3)*68 + r] = pv.w;
            float4 vv = *(const float4*)&g_qkv[(size_t)(b*Lseq + st*64 + r)*(3*Dm) + 2*Dm + h*AHDd + s4];
            *(float4*)&Vs[r*68 + s4] = vv;
        }
        __syncthreads();
#pragma unroll 8
        for (int s=0;s<64;s++){
            float4 a0 = *(const float4*)&PT[s*68 + ty*8];
            float4 a1 = *(const float4*)&PT[s*68 + ty*8 + 4];
            float4 xv = *(const float4*)&Vs[s*68 + tx*4];
            float a[8] = {a0.x,a0.y,a0.z,a0.w,a1.x,a1.y,a1.z,a1.w};
#pragma unroll
            for (int i=0;i<8;i++){
                acc[i][0] += a[i]*xv.x;
                acc[i][1] += a[i]*xv.y;
                acc[i][2] += a[i]*xv.z;
                acc[i][3] += a[i]*xv.w;
            }
        }
    }
#pragma unroll
    for (int i=0;i<8;i++){
        float4 v = make_float4(acc[i][0],acc[i][1],acc[i][2],acc[i][3]);
        *(float4*)&g_attnO[(size_t)(b*Lseq + tt*64 + ty*8+i)*Dm + h*AHDd + tx*4] = v;
    }
}

// ---------------- gMLP gate ----------------
__global__ void gelugate_kernel(){
    int idx = blockIdx.x*256 + threadIdx.x;
    int row = idx >> 9, c = idx & 511;
    float x1 = g_ff1[(size_t)row*(2*DFFd) + c];
    float x2 = g_ff1[(size_t)row*(2*DFFd) + DFFd + c];
    g_ff2[(size_t)row*DFFd + c] = geluf(x1)*x2;
}

// ---------------- mean over L ----------------
__global__ __launch_bounds__(1024)
void mean_kernel(){
    __shared__ float part[4][256];
    int b = blockIdx.x;
    int t = threadIdx.x;
    int d = t & 255, lg = t >> 8;
    float s = 0.f;
    for (int l = lg; l < Lseq; l += 4) s += g_lnbuf[(size_t)(b*Lseq + l)*Dm + d];
    part[lg][d] = s;
    __syncthreads();
    if (t < 256) g_hm[b*Dm + t] = (part[0][t]+part[1][t]+part[2][t]+part[3][t])*(1.f/Lseq);
}

// ---------------- output heads ----------------
__global__ void head_kernel(const float* __restrict__ dw, const float* __restrict__ db,
                            const float* __restrict__ rw, const float* __restrict__ rb,
                            float* __restrict__ out){
    int t = threadIdx.x; if (t >= 24) return;
    int which = t/12; int b = (t%12)/3; int j = t%3;
    const float* W  = which ? rw : dw;
    const float* bs = which ? rb : db;
    float acc = bs[j];
    for (int d = 0; d < Dm; d++) acc += g_hm[b*Dm + d]*W[d*3 + j];
    out[which*12 + b*3 + j] = acc;
}

// ---------------- launch ----------------
extern "C" void kernel_launch(void* const* d_in, const int* in_sizes, int n_in,
                              void* d_out, int out_size){
    const float* x          = (const float*)d_in[0];
    const float* pos_emb    = (const float*)d_in[1];
    const float* in_w       = (const float*)d_in[2];
    const float* in_b       = (const float*)d_in[3];
    const float* ln1_w      = (const float*)d_in[4];
    const float* ln1_b      = (const float*)d_in[5];
    const float* ssm_in_w   = (const float*)d_in[6];
    const float* ssm_conv_w = (const float*)d_in[7];
    const float* ssm_conv_b = (const float*)d_in[8];
    const float* ssm_dt_bias= (const float*)d_in[9];
    const float* ssm_A_log  = (const float*)d_in[10];
    const float* ssm_D      = (const float*)d_in[11];
    const float* ssm_norm_w = (const float*)d_in[12];
    const float* ssm_out_w  = (const float*)d_in[13];
    const float* ln2_w      = (const float*)d_in[14];
    const float* ln2_b      = (const float*)d_in[15];
    const float* fc1_w      = (const float*)d_in[16];
    const float* fc1_b      = (const float*)d_in[17];
    const float* fc2_w      = (const float*)d_in[18];
    const float* fc2_b      = (const float*)d_in[19];
    const float* attn_ln_w  = (const float*)d_in[20];
    const float* attn_ln_b  = (const float*)d_in[21];
    const float* attn_qkv_w = (const float*)d_in[22];
    const float* attn_qkv_b = (const float*)d_in[23];
    const float* attn_out_w = (const float*)d_in[24];
    const float* attn_out_b = (const float*)d_in[25];
    const float* norm_w     = (const float*)d_in[26];
    const float* norm_b     = (const float*)d_in[27];
    const float* dir_w      = (const float*)d_in[28];
    const float* dir_b      = (const float*)d_in[29];
    const float* reg_w      = (const float*)d_in[30];
    const float* reg_b      = (const float*)d_in[31];
    float* out = (float*)d_out;

    cudaFuncSetAttribute(mamba_kernel, cudaFuncAttributeMaxDynamicSharedMemorySize, MSMEM);

    float *ph, *pln, *pzx, *py, *pqkv, *pattnO, *pff1, *pff2;
    cudaGetSymbolAddress((void**)&ph,     g_h);
    cudaGetSymbolAddress((void**)&pln,    g_lnbuf);
    cudaGetSymbolAddress((void**)&pzx,    g_zx);
    cudaGetSymbolAddress((void**)&py,     g_y);
    cudaGetSymbolAddress((void**)&pqkv,   g_qkv);
    cudaGetSymbolAddress((void**)&pattnO, g_attnO);
    cudaGetSymbolAddress((void**)&pff1,   g_ff1);
    cudaGetSymbolAddress((void**)&pff2,   g_ff2);

    embed_kernel<<<ROWS, 256>>>(x, in_w, in_b, pos_emb);

    for (int i = 0; i < NLAY; i++){
        // ---- Mamba2 branch ----
        ln_kernel<<<ROWS, 256>>>(ph, ln1_w + i*Dm, ln1_b + i*Dm, pln);
        gemm128<<<dim3((DIPd+127)/128, ROWS/128), 256>>>(
            pln, ssm_in_w + (size_t)i*Dm*DIPd, nullptr, pzx, Dm, DIPd, 0);
        conv_silu_kernel<<<dim3(XBCd/128, ROWS), 128>>>(
            ssm_conv_w + (size_t)i*Kc*XBCd, ssm_conv_b + (size_t)i*XBCd);
        dtcum_kernel<<<Bb*Hh, 1024>>>(ssm_dt_bias + i*Hh, ssm_A_log + i*Hh);
        mamba_kernel<<<dim3(Lseq/64, Hh, Bb), 128, MSMEM>>>(ssm_D + i*Hh);
        gated_rms_kernel<<<ROWS, 256>>>(ssm_norm_w + (size_t)i*DI);
        gemm64<<<dim3(Dm/64, ROWS/128), 256>>>(
            py, ssm_out_w + (size_t)i*DI*Dm, nullptr, ph, DI, Dm, 1);

        // ---- attention (odd layers) ----
        if (i & 1){
            int j = i >> 1;
            ln_kernel<<<ROWS, 256>>>(ph, attn_ln_w + j*Dm, attn_ln_b + j*Dm, pln);
            gemm128<<<dim3(3*Dm/128, ROWS/128), 256>>>(
                pln, attn_qkv_w + (size_t)j*Dm*3*Dm, attn_qkv_b + (size_t)j*3*Dm, pqkv, Dm, 3*Dm, 0);
            attn_scores_kernel<<<dim3(256, AHn, Bb), 128>>>();
            softmax_kernel<<<Bb*AHn*Lseq, 256>>>();
            attn_pv_kernel<<<dim3(16, AHn, Bb), 128>>>();
            gemm64<<<dim3(Dm/64, ROWS/128), 256>>>(
                pattnO, attn_out_w + (size_t)j*Dm*Dm, attn_out_b + (size_t)j*Dm, ph, Dm, Dm, 1);
        }

        // ---- gMLP ----
        ln_kernel<<<ROWS, 256>>>(ph, ln2_w + i*Dm, ln2_b + i*Dm, pln);
        gemm128<<<dim3(2*DFFd/128, ROWS/128), 256>>>(
            pln, fc1_w + (size_t)i*Dm*2*DFFd, fc1_b + (size_t)i*2*DFFd, pff1, Dm, 2*DFFd, 0);
        gelugate_kernel<<<(ROWS*DFFd)/256, 256>>>();
        gemm64<<<dim3(Dm/64, ROWS/128), 256>>>(
            pff2, fc2_w + (size_t)i*DFFd*Dm, fc2_b + (size_t)i*Dm, ph, DFFd, Dm, 1);
    }

    // ---- final norm, mean, heads ----
    ln_kernel<<<ROWS, 256>>>(ph, norm_w, norm_b, pln);
    mean_kernel<<<Bb, 1024>>>();
    head_kernel<<<1, 32>>>(dir_w, dir_b, reg_w, reg_b, out);
}

// round 3
// speedup vs baseline: 1.0982x; 1.0221x over previous
#include <cuda_runtime.h>
#include <math.h>

// ---------------- problem constants ----------------
#define Bb 4
#define Lseq 1024
#define INDIM 46
#define Dm 256
#define DSm 64
#define Kc 4
#define NLAY 4
#define DI 512          // EXP*D
#define HDm 64
#define Hh 8            // DI/HD
#define XBCd 640        // DI + 2*DS
#define DIPd 1160       // 2*DI + 2*DS + H
#define DFFd 512
#define AHn 4
#define AHDd 64
#define ROWS (Bb*Lseq)  // 4096

typedef unsigned long long u64;

// ---------------- device scratch ----------------
__device__ float g_h[ROWS*Dm];
__device__ float g_lnbuf[ROWS*Dm];
__device__ float g_zx[ROWS*DIPd];
__device__ float g_xbc[ROWS*XBCd];
__device__ float g_dt[Bb*Hh*Lseq];
__device__ float g_cA[Bb*Hh*Lseq];
__device__ float g_y[ROWS*DI];
__device__ float g_qkv[ROWS*3*Dm];
__device__ float g_scores[(size_t)Bb*AHn*Lseq*Lseq];   // 64 MB
__device__ float g_attnO[ROWS*Dm];
__device__ float g_ff1[ROWS*2*DFFd];
__device__ float g_ff2[ROWS*DFFd];
__device__ float g_hm[Bb*Dm];

__device__ __forceinline__ float siluf(float x){ return x / (1.f + expf(-x)); }
__device__ __forceinline__ float geluf(float x){ return 0.5f*x*(1.f + erff(x*0.70710678118654752f)); }

// ---------------- packed fp32x2 helpers (Blackwell FFMA2 path) ----------------
__device__ __forceinline__ u64 pk2(float x){
    u64 r; asm("mov.b64 %0, {%1, %1};" : "=l"(r) : "f"(x)); return r;
}
__device__ __forceinline__ void fma2(u64 &d, u64 a, u64 b){
    asm("fma.rn.f32x2 %0, %1, %2, %0;" : "+l"(d) : "l"(a), "l"(b));
}
__device__ __forceinline__ float2 upk(u64 v){
    float2 f; asm("mov.b64 {%0, %1}, %2;" : "=f"(f.x), "=f"(f.y) : "l"(v)); return f;
}

// ---------------- embed ----------------
__global__ void embed_kernel(const float* __restrict__ x,
                             const float* __restrict__ in_w,
                             const float* __restrict__ in_b,
                             const float* __restrict__ pos){
    int row = blockIdx.x;
    int d = threadIdx.x;
    __shared__ float xr[INDIM];
    if (d < INDIM) xr[d] = x[(size_t)row*INDIM + d];
    __syncthreads();
    float acc = in_b[d];
#pragma unroll
    for (int i = 0; i < INDIM; i++) acc += xr[i]*in_w[i*Dm + d];
    int l = row & (Lseq-1);
    g_h[(size_t)row*Dm + d] = acc + pos[(size_t)l*Dm + d];
}

// ---------------- layernorm ----------------
__global__ void ln_kernel(const float* __restrict__ X,
                          const float* __restrict__ w,
                          const float* __restrict__ b,
                          float* __restrict__ out){
    int row = blockIdx.x; int t = threadIdx.x;
    __shared__ float red[256];
    float v = X[(size_t)row*Dm + t];
    red[t] = v; __syncthreads();
    for (int s = 128; s > 0; s >>= 1){ if (t < s) red[t] += red[t+s]; __syncthreads(); }
    float m = red[0]*(1.f/Dm);
    __syncthreads();
    float d0 = v - m;
    red[t] = d0*d0; __syncthreads();
    for (int s = 128; s > 0; s >>= 1){ if (t < s) red[t] += red[t+s]; __syncthreads(); }
    float var = red[0]*(1.f/Dm);
    out[(size_t)row*Dm + t] = d0*rsqrtf(var + 1e-5f)*w[t] + b[t];
}

// ---------------- SGEMM 128x128 tile, 8x8 micro (FFMA2), double-buffered ----------------
__global__ __launch_bounds__(256,2)
void gemm128(const float* __restrict__ A, const float* __restrict__ W,
             const float* __restrict__ bias, float* __restrict__ C,
             int K, int N, int addC){
    __shared__ float As[2][16][128];
    __shared__ float Bs[2][16][128];
    int tid = threadIdx.x;
    int row0 = blockIdx.y*128, col0 = blockIdx.x*128;
    int ar = tid>>1, ak = (tid&1)*8;
    int bk = tid>>4, bc = (tid&15)*8;
    int ty = tid>>4, tx = tid&15;
    const float* Ap = A + (size_t)(row0+ar)*K + ak;
    float4 a0,a1,b0,b1;
    a0 = *(const float4*)(Ap);
    a1 = *(const float4*)(Ap+4);
    b0 = make_float4(0.f,0.f,0.f,0.f); b1 = b0;
    if (col0+bc+4 <= N) b0 = *(const float4*)(W + (size_t)bk*N + col0+bc);
    if (col0+bc+8 <= N) b1 = *(const float4*)(W + (size_t)bk*N + col0+bc+4);
    int nt = K>>4;
    As[0][ak+0][ar]=a0.x; As[0][ak+1][ar]=a0.y; As[0][ak+2][ar]=a0.z; As[0][ak+3][ar]=a0.w;
    As[0][ak+4][ar]=a1.x; As[0][ak+5][ar]=a1.y; As[0][ak+6][ar]=a1.z; As[0][ak+7][ar]=a1.w;
    *(float4*)&Bs[0][bk][bc]   = b0;
    *(float4*)&Bs[0][bk][bc+4] = b1;
    __syncthreads();
    u64 acc2[8][4];
#pragma unroll
    for (int i=0;i<8;i++)
#pragma unroll
        for (int j=0;j<4;j++) acc2[i][j]=0ULL;
    for (int t=0; t<nt; t++){
        if (t+1 < nt){
            int k0 = (t+1)*16;
            a0 = *(const float4*)(Ap + k0);
            a1 = *(const float4*)(Ap + k0 + 4);
            b0 = make_float4(0.f,0.f,0.f,0.f); b1 = b0;
            if (col0+bc+4 <= N) b0 = *(const float4*)(W + (size_t)(k0+bk)*N + col0+bc);
            if (col0+bc+8 <= N) b1 = *(const float4*)(W + (size_t)(k0+bk)*N + col0+bc+4);
        }
        int buf = t&1;
#pragma unroll
        for (int k=0;k<16;k++){
            float4 av0 = *(const float4*)&As[buf][k][ty*8];
            float4 av1 = *(const float4*)&As[buf][k][ty*8+4];
            ulonglong2 bp0 = *(const ulonglong2*)&Bs[buf][k][tx*4];
            ulonglong2 bp1 = *(const ulonglong2*)&Bs[buf][k][64+tx*4];
            u64 ap[8];
            ap[0]=pk2(av0.x); ap[1]=pk2(av0.y); ap[2]=pk2(av0.z); ap[3]=pk2(av0.w);
            ap[4]=pk2(av1.x); ap[5]=pk2(av1.y); ap[6]=pk2(av1.z); ap[7]=pk2(av1.w);
#pragma unroll
            for (int i=0;i<8;i++){
                fma2(acc2[i][0], ap[i], bp0.x);
                fma2(acc2[i][1], ap[i], bp0.y);
                fma2(acc2[i][2], ap[i], bp1.x);
                fma2(acc2[i][3], ap[i], bp1.y);
            }
        }
        __syncthreads();
        if (t+1 < nt){
            int nb = (t+1)&1;
            As[nb][ak+0][ar]=a0.x; As[nb][ak+1][ar]=a0.y; As[nb][ak+2][ar]=a0.z; As[nb][ak+3][ar]=a0.w;
            As[nb][ak+4][ar]=a1.x; As[nb][ak+5][ar]=a1.y; As[nb][ak+6][ar]=a1.z; As[nb][ak+7][ar]=a1.w;
            *(float4*)&Bs[nb][bk][bc]   = b0;
            *(float4*)&Bs[nb][bk][bc+4] = b1;
            __syncthreads();
        }
    }
#pragma unroll
    for (int half=0; half<2; half++){
        int cbase = col0 + half*64 + tx*4;
        if (cbase + 4 <= N){
            float bx=0.f,by=0.f,bz=0.f,bw=0.f;
            if (bias){ bx=bias[cbase]; by=bias[cbase+1]; bz=bias[cbase+2]; bw=bias[cbase+3]; }
#pragma unroll
            for (int i=0;i<8;i++){
                int r = row0 + ty*8 + i;
                size_t idx = (size_t)r*N + cbase;
                float2 p0 = upk(acc2[i][half*2+0]);
                float2 p1 = upk(acc2[i][half*2+1]);
                float4 v;
                v.x = p0.x+bx; v.y = p0.y+by; v.z = p1.x+bz; v.w = p1.y+bw;
                if (addC){
                    float4 o = *(const float4*)&C[idx];
                    v.x+=o.x; v.y+=o.y; v.z+=o.z; v.w+=o.w;
                }
                *(float4*)&C[idx] = v;
            }
        }
    }
}

// ---------------- SGEMM 128x64 tile, 8x4 micro (FFMA2), double-buffered ----------------
__global__ __launch_bounds__(256,2)
void gemm64(const float* __restrict__ A, const float* __restrict__ W,
            const float* __restrict__ bias, float* __restrict__ C,
            int K, int N, int addC){
    __shared__ float As[2][16][128];
    __shared__ float Bs[2][16][64];
    int tid = threadIdx.x;
    int row0 = blockIdx.y*128, col0 = blockIdx.x*64;
    int ar = tid>>1, ak = (tid&1)*8;
    int bk = tid>>4, bc = (tid&15)*4;
    int ty = tid>>4, tx = tid&15;
    const float* Ap = A + (size_t)(row0+ar)*K + ak;
    float4 a0,a1,b0;
    a0 = *(const float4*)(Ap);
    a1 = *(const float4*)(Ap+4);
    b0 = *(const float4*)(W + (size_t)bk*N + col0+bc);
    int nt = K>>4;
    As[0][ak+0][ar]=a0.x; As[0][ak+1][ar]=a0.y; As[0][ak+2][ar]=a0.z; As[0][ak+3][ar]=a0.w;
    As[0][ak+4][ar]=a1.x; As[0][ak+5][ar]=a1.y; As[0][ak+6][ar]=a1.z; As[0][ak+7][ar]=a1.w;
    *(float4*)&Bs[0][bk][bc] = b0;
    __syncthreads();
    u64 acc2[8][2];
#pragma unroll
    for (int i=0;i<8;i++){ acc2[i][0]=0ULL; acc2[i][1]=0ULL; }
    for (int t=0; t<nt; t++){
        if (t+1 < nt){
            int k0 = (t+1)*16;
            a0 = *(const float4*)(Ap + k0);
            a1 = *(const float4*)(Ap + k0 + 4);
            b0 = *(const float4*)(W + (size_t)(k0+bk)*N + col0+bc);
        }
        int buf = t&1;
#pragma unroll
        for (int k=0;k<16;k++){
            float4 av0 = *(const float4*)&As[buf][k][ty*8];
            float4 av1 = *(const float4*)&As[buf][k][ty*8+4];
            ulonglong2 bp = *(const ulonglong2*)&Bs[buf][k][tx*4];
            u64 ap[8];
            ap[0]=pk2(av0.x); ap[1]=pk2(av0.y); ap[2]=pk2(av0.z); ap[3]=pk2(av0.w);
            ap[4]=pk2(av1.x); ap[5]=pk2(av1.y); ap[6]=pk2(av1.z); ap[7]=pk2(av1.w);
#pragma unroll
            for (int i=0;i<8;i++){
                fma2(acc2[i][0], ap[i], bp.x);
                fma2(acc2[i][1], ap[i], bp.y);
            }
        }
        __syncthreads();
        if (t+1 < nt){
            int nb = (t+1)&1;
            As[nb][ak+0][ar]=a0.x; As[nb][ak+1][ar]=a0.y; As[nb][ak+2][ar]=a0.z; As[nb][ak+3][ar]=a0.w;
            As[nb][ak+4][ar]=a1.x; As[nb][ak+5][ar]=a1.y; As[nb][ak+6][ar]=a1.z; As[nb][ak+7][ar]=a1.w;
            *(float4*)&Bs[nb][bk][bc] = b0;
            __syncthreads();
        }
    }
    int cbase = col0 + tx*4;
    float bx=0.f,by=0.f,bz=0.f,bw=0.f;
    if (bias){ bx=bias[cbase]; by=bias[cbase+1]; bz=bias[cbase+2]; bw=bias[cbase+3]; }
#pragma unroll
    for (int i=0;i<8;i++){
        int r = row0 + ty*8 + i;
        size_t idx = (size_t)r*N + cbase;
        float2 p0 = upk(acc2[i][0]);
        float2 p1 = upk(acc2[i][1]);
        float4 v;
        v.x = p0.x+bx; v.y = p0.y+by; v.z = p1.x+bz; v.w = p1.y+bw;
        if (addC){
            float4 o = *(const float4*)&C[idx];
            v.x+=o.x; v.y+=o.y; v.z+=o.z; v.w+=o.w;
        }
        *(float4*)&C[idx] = v;
    }
}

// ---------------- conv + silu ----------------
__global__ void conv_silu_kernel(const float* __restrict__ cw,
                                 const float* __restrict__ cb){
    int c = blockIdx.x*128 + threadIdx.x;
    int row = blockIdx.y;
    int l = row & (Lseq-1);
    float acc = cb[c];
#pragma unroll
    for (int k = 0; k < Kc; k++){
        int ls = l + k - (Kc-1);
        if (ls >= 0)
            acc += g_zx[(size_t)(row + k - (Kc-1))*DIPd + DI + c] * cw[k*XBCd + c];
    }
    g_xbc[(size_t)row*XBCd + c] = siluf(acc);
}

// ---------------- fused dt softplus + cumsum ----------------
__global__ __launch_bounds__(1024)
void dtcum_kernel(const float* __restrict__ dt_bias,
                  const float* __restrict__ A_log){
    int bh = blockIdx.x; int b = bh>>3, h = bh&7;
    int l = threadIdx.x;
    __shared__ float buf[1024];
    float raw = g_zx[(size_t)(b*Lseq+l)*DIPd + DI + XBCd + h] + dt_bias[h];
    float dtv = (raw > 20.f) ? raw : log1pf(expf(raw));
    g_dt[(size_t)bh*Lseq + l] = dtv;
    buf[l] = dtv * (-expf(A_log[h]));
    __syncthreads();
    for (int off = 1; off < 1024; off <<= 1){
        float add = (l >= off) ? buf[l-off] : 0.f;
        __syncthreads();
        buf[l] += add;
        __syncthreads();
    }
    g_cA[(size_t)bh*Lseq + l] = buf[l];
}

// ---------------- fused Mamba2 quadratic form (128 thr, 8x4 micro, FFMA2) ----------------
#define MSMEM ((3*64*68 + 3*64)*4)
__global__ __launch_bounds__(128)
void mamba_kernel(const float* __restrict__ Dvec){
    extern __shared__ float sm[];
    float* CtT = sm;             // [n][68] : C transposed
    float* BsS = CtT + 64*68;    // BsT [n][68], then ST [s][68]
    float* Xs  = BsS + 64*68;    // [s][68]
    float* cAt = Xs + 64*68;
    float* cAs = cAt + 64;
    float* dss = cAs + 64;
    int tt = blockIdx.x, h = blockIdx.y, b = blockIdx.z;
    int tid = threadIdx.x;
    int ty = tid>>4, tx = tid&15;
    size_t rowt = (size_t)(b*Lseq + tt*64);

#pragma unroll
    for (int c=0;c<8;c++){
        int idx = c*128 + tid;
        int r = idx>>4, n4 = (idx&15)*4;
        float4 v = *(const float4*)&g_xbc[(rowt + r)*XBCd + DI + DSm + n4];
        CtT[(n4+0)*68 + r] = v.x;
        CtT[(n4+1)*68 + r] = v.y;
        CtT[(n4+2)*68 + r] = v.z;
        CtT[(n4+3)*68 + r] = v.w;
    }
    if (tid < 64) cAt[tid] = g_cA[(size_t)(b*Hh+h)*Lseq + tt*64 + tid];

    u64 yacc2[8][2];
#pragma unroll
    for (int i=0;i<8;i++){ yacc2[i][0]=0ULL; yacc2[i][1]=0ULL; }

    for (int st=0; st<=tt; st++){
        __syncthreads();
        size_t rows = (size_t)(b*Lseq + st*64);
#pragma unroll
        for (int c=0;c<8;c++){
            int idx = c*128 + tid;
            int r = idx>>4, n4 = (idx&15)*4;
            float4 bv = *(const float4*)&g_xbc[(rows+r)*XBCd + DI + n4];
            BsS[(n4+0)*68 + r] = bv.x;
            BsS[(n4+1)*68 + r] = bv.y;
            BsS[(n4+2)*68 + r] = bv.z;
            BsS[(n4+3)*68 + r] = bv.w;
            float4 xv = *(const float4*)&g_xbc[(rows+r)*XBCd + h*HDm + n4];
            *(float4*)&Xs[r*68 + n4] = xv;
        }
        if (tid < 64){
            cAs[tid] = g_cA[(size_t)(b*Hh+h)*Lseq + st*64 + tid];
            dss[tid] = g_dt[(size_t)(b*Hh+h)*Lseq + st*64 + tid];
        }
        __syncthreads();
        // CB = C_t . B_s^T  (reduce over n), packed accumulators
        u64 cb2[8][2];
#pragma unroll
        for (int i=0;i<8;i++){ cb2[i][0]=0ULL; cb2[i][1]=0ULL; }
#pragma unroll 8
        for (int n=0;n<64;n++){
            float4 a0 = *(const float4*)&CtT[n*68 + ty*8];
            float4 a1 = *(const float4*)&CtT[n*68 + ty*8 + 4];
            ulonglong2 bp = *(const ulonglong2*)&BsS[n*68 + tx*4];
            u64 ap[8];
            ap[0]=pk2(a0.x); ap[1]=pk2(a0.y); ap[2]=pk2(a0.z); ap[3]=pk2(a0.w);
            ap[4]=pk2(a1.x); ap[5]=pk2(a1.y); ap[6]=pk2(a1.z); ap[7]=pk2(a1.w);
#pragma unroll
            for (int i=0;i<8;i++){
                fma2(cb2[i][0], ap[i], bp.x);
                fma2(cb2[i][1], ap[i], bp.y);
            }
        }
        __syncthreads();
        // decay/dt, store S transposed: ST[s][t]
        bool diag = (st == tt);
        float d[8][4];
#pragma unroll
        for (int i=0;i<8;i++){
            int t = ty*8+i;
            float ca = cAt[t];
            float2 p0 = upk(cb2[i][0]);
            float2 p1 = upk(cb2[i][1]);
            float cbv[4] = {p0.x, p0.y, p1.x, p1.y};
#pragma unroll
            for (int j=0;j<4;j++){
                int s = tx*4+j;
                float v = 0.f;
                if (!diag || s <= t) v = expf(ca - cAs[s]) * cbv[j] * dss[s];
                d[i][j] = v;
            }
        }
#pragma unroll
        for (int j=0;j<4;j++){
            int s = tx*4+j;
            float4 v0 = make_float4(d[0][j],d[1][j],d[2][j],d[3][j]);
            float4 v1 = make_float4(d[4][j],d[5][j],d[6][j],d[7][j]);
            *(float4*)&BsS[s*68 + ty*8]   = v0;
            *(float4*)&BsS[s*68 + ty*8+4] = v1;
        }
        __syncthreads();
        // y += S @ X  (reduce over s)
#pragma unroll 8
        for (int s=0;s<64;s++){
            float4 a0 = *(const float4*)&BsS[s*68 + ty*8];
            float4 a1 = *(const float4*)&BsS[s*68 + ty*8 + 4];
            ulonglong2 xp = *(const ulonglong2*)&Xs[s*68 + tx*4];
            u64 ap[8];
            ap[0]=pk2(a0.x); ap[1]=pk2(a0.y); ap[2]=pk2(a0.z); ap[3]=pk2(a0.w);
            ap[4]=pk2(a1.x); ap[5]=pk2(a1.y); ap[6]=pk2(a1.z); ap[7]=pk2(a1.w);
#pragma unroll
            for (int i=0;i<8;i++){
                fma2(yacc2[i][0], ap[i], xp.x);
                fma2(yacc2[i][1], ap[i], xp.y);
            }
        }
    }
    float Dh = Dvec[h];
#pragma unroll
    for (int i=0;i<8;i++){
        int t = ty*8+i;
        float4 xv = *(const float4*)&g_xbc[(rowt+t)*XBCd + h*HDm + tx*4];
        float2 p0 = upk(yacc2[i][0]);
        float2 p1 = upk(yacc2[i][1]);
        float4 o;
        o.x = p0.x + Dh*xv.x;
        o.y = p0.y + Dh*xv.y;
        o.z = p1.x + Dh*xv.z;
        o.w = p1.y + Dh*xv.w;
        *(float4*)&g_y[(rowt+t)*DI + h*HDm + tx*4] = o;
    }
}

// ---------------- gated RMS norm ----------------
__global__ void gated_rms_kernel(const float* __restrict__ nw){
    int row = blockIdx.x; int t = threadIdx.x;
    __shared__ float red[256];
    float z0 = g_zx[(size_t)row*DIPd + t];
    float z1 = g_zx[(size_t)row*DIPd + t + 256];
    float y0 = g_y[(size_t)row*DI + t];
    float y1 = g_y[(size_t)row*DI + t + 256];
    float gg0 = y0 * siluf(z0);
    float gg1 = y1 * siluf(z1);
    red[t] = gg0*gg0 + gg1*gg1; __syncthreads();
    for (int s = 128; s > 0; s >>= 1){ if (t < s) red[t] += red[t+s]; __syncthreads(); }
    float scale = rsqrtf(red[0]*(1.f/DI) + 1e-5f);
    g_y[(size_t)row*DI + t]       = gg0*scale*nw[t];
    g_y[(size_t)row*DI + t + 256] = gg1*scale*nw[t+256];
}

// ---------------- attention scores (128 thr, 8x4 micro, FFMA2) ----------------
__global__ __launch_bounds__(128)
void attn_scores_kernel(){
    __shared__ float QT[64*68];
    __shared__ float KT[64*68];
    int tt = blockIdx.x >> 4, st = blockIdx.x & 15;
    int h = blockIdx.y, b = blockIdx.z;
    int tid = threadIdx.x;
    int ty = tid>>4, tx = tid&15;
#pragma unroll
    for (int c=0;c<8;c++){
        int idx = c*128 + tid;
        int r = idx>>4, p4 = (idx&15)*4;
        float4 q = *(const float4*)&g_qkv[(size_t)(b*Lseq + tt*64 + r)*(3*Dm) + h*AHDd + p4];
        QT[(p4+0)*68 + r] = q.x;
        QT[(p4+1)*68 + r] = q.y;
        QT[(p4+2)*68 + r] = q.z;
        QT[(p4+3)*68 + r] = q.w;
        float4 k = *(const float4*)&g_qkv[(size_t)(b*Lseq + st*64 + r)*(3*Dm) + Dm + h*AHDd + p4];
        KT[(p4+0)*68 + r] = k.x;
        KT[(p4+1)*68 + r] = k.y;
        KT[(p4+2)*68 + r] = k.z;
        KT[(p4+3)*68 + r] = k.w;
    }
    __syncthreads();
    u64 acc2[8][2];
#pragma unroll
    for (int i=0;i<8;i++){ acc2[i][0]=0ULL; acc2[i][1]=0ULL; }
#pragma unroll 8
    for (int p=0;p<64;p++){
        float4 a0 = *(const float4*)&QT[p*68 + ty*8];
        float4 a1 = *(const float4*)&QT[p*68 + ty*8 + 4];
        ulonglong2 bp = *(const ulonglong2*)&KT[p*68 + tx*4];
        u64 ap[8];
        ap[0]=pk2(a0.x); ap[1]=pk2(a0.y); ap[2]=pk2(a0.z); ap[3]=pk2(a0.w);
        ap[4]=pk2(a1.x); ap[5]=pk2(a1.y); ap[6]=pk2(a1.z); ap[7]=pk2(a1.w);
#pragma unroll
        for (int i=0;i<8;i++){
            fma2(acc2[i][0], ap[i], bp.x);
            fma2(acc2[i][1], ap[i], bp.y);
        }
    }
    size_t base = ((size_t)((b*AHn+h)*Lseq + tt*64))*Lseq + st*64;
#pragma unroll
    for (int i=0;i<8;i++){
        float2 p0 = upk(acc2[i][0]);
        float2 p1 = upk(acc2[i][1]);
        float4 v = make_float4(p0.x*0.125f, p0.y*0.125f, p1.x*0.125f, p1.y*0.125f);
        *(float4*)&g_scores[base + (size_t)(ty*8+i)*Lseq + tx*4] = v;
    }
}

// ---------------- softmax ----------------
__global__ void softmax_kernel(){
    int row = blockIdx.x; int t = threadIdx.x;
    __shared__ float red[256];
    size_t base = (size_t)row*Lseq;
    float v[4];
#pragma unroll
    for (int k = 0; k < 4; k++) v[k] = g_scores[base + t + k*256];
    float m = fmaxf(fmaxf(v[0],v[1]), fmaxf(v[2],v[3]));
    red[t] = m; __syncthreads();
    for (int s = 128; s > 0; s >>= 1){ if (t < s) red[t] = fmaxf(red[t], red[t+s]); __syncthreads(); }
    m = red[0];
    __syncthreads();
    float ls = 0.f;
#pragma unroll
    for (int k = 0; k < 4; k++){ v[k] = expf(v[k]-m); ls += v[k]; }
    red[t] = ls; __syncthreads();
    for (int s = 128; s > 0; s >>= 1){ if (t < s) red[t] += red[t+s]; __syncthreads(); }
    float inv = 1.f/red[0];
#pragma unroll
    for (int k = 0; k < 4; k++) g_scores[base + t + k*256] = v[k]*inv;
}

// ---------------- PV (128 thr, 8x4 micro, FFMA2) ----------------
__global__ __launch_bounds__(128)
void attn_pv_kernel(){
    __shared__ float PT[64*68];
    __shared__ float Vs[64*68];
    int tt = blockIdx.x, h = blockIdx.y, b = blockIdx.z;
    int tid = threadIdx.x;
    int ty = tid>>4, tx = tid&15;
    u64 acc2[8][2];
#pragma unroll
    for (int i=0;i<8;i++){ acc2[i][0]=0ULL; acc2[i][1]=0ULL; }
    for (int st=0; st<16; st++){
        __syncthreads();
#pragma unroll
        for (int c=0;c<8;c++){
            int idx = c*128 + tid;
            int r = idx>>4, s4 = (idx&15)*4;
            float4 pv = *(const float4*)&g_scores[((size_t)((b*AHn+h)*Lseq + tt*64 + r))*Lseq + st*64 + s4];
            PT[(s4+0)*68 + r] = pv.x;
            PT[(s4+1)*68 + r] = pv.y;
            PT[(s4+2)*68 + r] = pv.z;
            PT[(s4+3)*68 + r] = pv.w;
            float4 vv = *(const float4*)&g_qkv[(size_t)(b*Lseq + st*64 + r)*(3*Dm) + 2*Dm + h*AHDd + s4];
            *(float4*)&Vs[r*68 + s4] = vv;
        }
        __syncthreads();
#pragma unroll 8
        for (int s=0;s<64;s++){
            float4 a0 = *(const float4*)&PT[s*68 + ty*8];
            float4 a1 = *(const float4*)&PT[s*68 + ty*8 + 4];
            ulonglong2 xp = *(const ulonglong2*)&Vs[s*68 + tx*4];
            u64 ap[8];
            ap[0]=pk2(a0.x); ap[1]=pk2(a0.y); ap[2]=pk2(a0.z); ap[3]=pk2(a0.w);
            ap[4]=pk2(a1.x); ap[5]=pk2(a1.y); ap[6]=pk2(a1.z); ap[7]=pk2(a1.w);
#pragma unroll
            for (int i=0;i<8;i++){
                fma2(acc2[i][0], ap[i], xp.x);
                fma2(acc2[i][1], ap[i], xp.y);
            }
        }
    }
#pragma unroll
    for (int i=0;i<8;i++){
        float2 p0 = upk(acc2[i][0]);
        float2 p1 = upk(acc2[i][1]);
        float4 v = make_float4(p0.x,p0.y,p1.x,p1.y);
        *(float4*)&g_attnO[(size_t)(b*Lseq + tt*64 + ty*8+i)*Dm + h*AHDd + tx*4] = v;
    }
}

// ---------------- gMLP gate ----------------
__global__ void gelugate_kernel(){
    int idx = blockIdx.x*256 + threadIdx.x;
    int row = idx >> 9, c = idx & 511;
    float x1 = g_ff1[(size_t)row*(2*DFFd) + c];
    float x2 = g_ff1[(size_t)row*(2*DFFd) + DFFd + c];
    g_ff2[(size_t)row*DFFd + c] = geluf(x1)*x2;
}

// ---------------- mean over L ----------------
__global__ __launch_bounds__(1024)
void mean_kernel(){
    __shared__ float part[4][256];
    int b = blockIdx.x;
    int t = threadIdx.x;
    int d = t & 255, lg = t >> 8;
    float s = 0.f;
    for (int l = lg; l < Lseq; l += 4) s += g_lnbuf[(size_t)(b*Lseq + l)*Dm + d];
    part[lg][d] = s;
    __syncthreads();
    if (t < 256) g_hm[b*Dm + t] = (part[0][t]+part[1][t]+part[2][t]+part[3][t])*(1.f/Lseq);
}

// ---------------- output heads ----------------
__global__ void head_kernel(const float* __restrict__ dw, const float* __restrict__ db,
                            const float* __restrict__ rw, const float* __restrict__ rb,
                            float* __restrict__ out){
    int t = threadIdx.x; if (t >= 24) return;
    int which = t/12; int b = (t%12)/3; int j = t%3;
    const float* W  = which ? rw : dw;
    const float* bs = which ? rb : db;
    float acc = bs[j];
    for (int d = 0; d < Dm; d++) acc += g_hm[b*Dm + d]*W[d*3 + j];
    out[which*12 + b*3 + j] = acc;
}

// ---------------- launch ----------------
extern "C" void kernel_launch(void* const* d_in, const int* in_sizes, int n_in,
                              void* d_out, int out_size){
    const float* x          = (const float*)d_in[0];
    const float* pos_emb    = (const float*)d_in[1];
    const float* in_w       = (const float*)d_in[2];
    const float* in_b       = (const float*)d_in[3];
    const float* ln1_w      = (const float*)d_in[4];
    const float* ln1_b      = (const float*)d_in[5];
    const float* ssm_in_w   = (const float*)d_in[6];
    const float* ssm_conv_w = (const float*)d_in[7];
    const float* ssm_conv_b = (const float*)d_in[8];
    const float* ssm_dt_bias= (const float*)d_in[9];
    const float* ssm_A_log  = (const float*)d_in[10];
    const float* ssm_D      = (const float*)d_in[11];
    const float* ssm_norm_w = (const float*)d_in[12];
    const float* ssm_out_w  = (const float*)d_in[13];
    const float* ln2_w      = (const float*)d_in[14];
    const float* ln2_b      = (const float*)d_in[15];
    const float* fc1_w      = (const float*)d_in[16];
    const float* fc1_b      = (const float*)d_in[17];
    const float* fc2_w      = (const float*)d_in[18];
    const float* fc2_b      = (const float*)d_in[19];
    const float* attn_ln_w  = (const float*)d_in[20];
    const float* attn_ln_b  = (const float*)d_in[21];
    const float* attn_qkv_w = (const float*)d_in[22];
    const float* attn_qkv_b = (const float*)d_in[23];
    const float* attn_out_w = (const float*)d_in[24];
    const float* attn_out_b = (const float*)d_in[25];
    const float* norm_w     = (const float*)d_in[26];
    const float* norm_b     = (const float*)d_in[27];
    const float* dir_w      = (const float*)d_in[28];
    const float* dir_b      = (const float*)d_in[29];
    const float* reg_w      = (const float*)d_in[30];
    const float* reg_b      = (const float*)d_in[31];
    float* out = (float*)d_out;

    cudaFuncSetAttribute(mamba_kernel, cudaFuncAttributeMaxDynamicSharedMemorySize, MSMEM);

    float *ph, *pln, *pzx, *py, *pqkv, *pattnO, *pff1, *pff2;
    cudaGetSymbolAddress((void**)&ph,     g_h);
    cudaGetSymbolAddress((void**)&pln,    g_lnbuf);
    cudaGetSymbolAddress((void**)&pzx,    g_zx);
    cudaGetSymbolAddress((void**)&py,     g_y);
    cudaGetSymbolAddress((void**)&pqkv,   g_qkv);
    cudaGetSymbolAddress((void**)&pattnO, g_attnO);
    cudaGetSymbolAddress((void**)&pff1,   g_ff1);
    cudaGetSymbolAddress((void**)&pff2,   g_ff2);

    embed_kernel<<<ROWS, 256>>>(x, in_w, in_b, pos_emb);

    for (int i = 0; i < NLAY; i++){
        // ---- Mamba2 branch ----
        ln_kernel<<<ROWS, 256>>>(ph, ln1_w + i*Dm, ln1_b + i*Dm, pln);
        gemm128<<<dim3((DIPd+127)/128, ROWS/128), 256>>>(
            pln, ssm_in_w + (size_t)i*Dm*DIPd, nullptr, pzx, Dm, DIPd, 0);
        conv_silu_kernel<<<dim3(XBCd/128, ROWS), 128>>>(
            ssm_conv_w + (size_t)i*Kc*XBCd, ssm_conv_b + (size_t)i*XBCd);
        dtcum_kernel<<<Bb*Hh, 1024>>>(ssm_dt_bias + i*Hh, ssm_A_log + i*Hh);
        mamba_kernel<<<dim3(Lseq/64, Hh, Bb), 128, MSMEM>>>(ssm_D + i*Hh);
        gated_rms_kernel<<<ROWS, 256>>>(ssm_norm_w + (size_t)i*DI);
        gemm64<<<dim3(Dm/64, ROWS/128), 256>>>(
            py, ssm_out_w + (size_t)i*DI*Dm, nullptr, ph, DI, Dm, 1);

        // ---- attention (odd layers) ----
        if (i & 1){
            int j = i >> 1;
            ln_kernel<<<ROWS, 256>>>(ph, attn_ln_w + j*Dm, attn_ln_b + j*Dm, pln);
            gemm128<<<dim3(3*Dm/128, ROWS/128), 256>>>(
                pln, attn_qkv_w + (size_t)j*Dm*3*Dm, attn_qkv_b + (size_t)j*3*Dm, pqkv, Dm, 3*Dm, 0);
            attn_scores_kernel<<<dim3(256, AHn, Bb), 128>>>();
            softmax_kernel<<<Bb*AHn*Lseq, 256>>>();
            attn_pv_kernel<<<dim3(16, AHn, Bb), 128>>>();
            gemm64<<<dim3(Dm/64, ROWS/128), 256>>>(
                pattnO, attn_out_w + (size_t)j*Dm*Dm, attn_out_b + (size_t)j*Dm, ph, Dm, Dm, 1);
        }

        // ---- gMLP ----
        ln_kernel<<<ROWS, 256>>>(ph, ln2_w + i*Dm, ln2_b + i*Dm, pln);
        gemm128<<<dim3(2*DFFd/128, ROWS/128), 256>>>(
            pln, fc1_w + (size_t)i*Dm*2*DFFd, fc1_b + (size_t)i*2*DFFd, pff1, Dm, 2*DFFd, 0);
        gelugate_kernel<<<(ROWS*DFFd)/256, 256>>>();
        gemm64<<<dim3(Dm/64, ROWS/128), 256>>>(
            pff2, fc2_w + (size_t)i*DFFd*Dm, fc2_b + (size_t)i*Dm, ph, DFFd, Dm, 1);
    }

    // ---- final norm, mean, heads ----
    ln_kernel<<<ROWS, 256>>>(ph, norm_w, norm_b, pln);
    mean_kernel<<<Bb, 1024>>>();
    head_kernel<<<1, 32>>>(dir_w, dir_b, reg_w, reg_b, out);
}